// round 1
// baseline (speedup 1.0000x reference)
#include <cuda_runtime.h>

#define M_        8
#define E_        256
#define H_        256
#define L_        16384
#define D_        32
#define NPOS      1024          // D_*D_
#define NSPECIAL_ 32
#define SIDX_     8
#define NPLAYERS_ 4
#define POL_STRIDE (L_ + SIDX_) // 16392

// scratch (no cudaMalloc allowed)
__device__ float g_tab[M_ * NPOS * 2];  // [m][p][k]  64 KB
__device__ float g_clsdot[M_];          // cls-part of policy dot, includes bp

// ---------------------------------------------------------------------------
// Kernel A: value head, special head, cls_dot.  Launch <<<2, 256>>>.
//   block 0: special head + cls_dot (+ gather via special_move_idxs)
//   block 1: value head
// ---------------------------------------------------------------------------
__global__ void mlp_kernel(const float* __restrict__ cls,
                           const int*   __restrict__ sidx,
                           const float* __restrict__ Wp,  const float* __restrict__ bp,
                           const float* __restrict__ Wv1, const float* __restrict__ bv1,
                           const float* __restrict__ Wv2, const float* __restrict__ bv2,
                           const float* __restrict__ Ws1, const float* __restrict__ bs1,
                           const float* __restrict__ Ws2, const float* __restrict__ bs2,
                           float* __restrict__ out)
{
    __shared__ float sh_cls[M_ * E_];
    __shared__ float sh_h[M_][H_];
    __shared__ float sh_spec[M_][NSPECIAL_];
    const int tid = threadIdx.x;

    for (int i = tid; i < M_ * E_; i += 256) sh_cls[i] = cls[i];
    __syncthreads();

    if (blockIdx.x == 0) {
        // ---- cls_dot: one warp per m (8 warps = 256 threads) ----
        {
            const int w = tid >> 5, lane = tid & 31;
            float a = 0.f;
            for (int e = lane; e < E_; e += 32)
                a += sh_cls[w * E_ + e] * __ldg(&Wp[2 * E_ + e]);
            #pragma unroll
            for (int o = 16; o; o >>= 1) a += __shfl_xor_sync(0xffffffffu, a, o);
            if (lane == 0) g_clsdot[w] = a + __ldg(bp);
        }

        // ---- hidden = relu(cls @ Ws1 + bs1): thread tid owns column j=tid ----
        float acc[M_];
        #pragma unroll
        for (int m = 0; m < M_; m++) acc[m] = __ldg(&bs1[tid]);
        for (int e = 0; e < E_; e++) {
            const float wv = __ldg(&Ws1[e * H_ + tid]);
            #pragma unroll
            for (int m = 0; m < M_; m++) acc[m] += sh_cls[m * E_ + e] * wv;
        }
        #pragma unroll
        for (int m = 0; m < M_; m++) sh_h[m][tid] = fmaxf(acc[m], 0.f);
        __syncthreads();

        // ---- special_all = h @ Ws2 + bs2 : 8m x 32s = 256 threads ----
        {
            const int m = tid >> 5, s = tid & 31;
            float a = __ldg(&bs2[s]);
            for (int j = 0; j < H_; j++)
                a += sh_h[m][j] * __ldg(&Ws2[j * NSPECIAL_ + s]);
            sh_spec[m][s] = a;
        }
        __syncthreads();

        // ---- gather via special_move_idxs and write ----
        if (tid < M_ * SIDX_) {
            const int m = tid / SIDX_, i = tid % SIDX_;
            out[m * POL_STRIDE + L_ + i] = sh_spec[m][__ldg(&sidx[i])];
        }
    } else {
        // ---- value head ----
        float acc[M_];
        #pragma unroll
        for (int m = 0; m < M_; m++) acc[m] = __ldg(&bv1[tid]);
        for (int e = 0; e < E_; e++) {
            const float wv = __ldg(&Wv1[e * H_ + tid]);
            #pragma unroll
            for (int m = 0; m < M_; m++) acc[m] += sh_cls[m * E_ + e] * wv;
        }
        #pragma unroll
        for (int m = 0; m < M_; m++) sh_h[m][tid] = fmaxf(acc[m], 0.f);
        __syncthreads();

        if (tid < M_ * NPLAYERS_) {
            const int m = tid / NPLAYERS_, n = tid % NPLAYERS_;
            float a = __ldg(&bv2[n]);
            for (int j = 0; j < H_; j++)
                a += sh_h[m][j] * __ldg(&Wv2[j * NPLAYERS_ + n]);
            out[M_ * POL_STRIDE + m * NPLAYERS_ + n] = a;
        }
    }
}

// ---------------------------------------------------------------------------
// Kernel B: per-position dot table.
//   tab[m][p][0] = dot(emb[m,p,:], Wp[0:256]);  tab[m][p][1] = dot(..., Wp[256:512])
//   One warp per (m,p).  <<<1024, 256>>> -> 8192 warps.  Reads embedding once (8 MB).
// ---------------------------------------------------------------------------
__global__ void table_kernel(const float* __restrict__ emb,
                             const float* __restrict__ Wp)
{
    __shared__ float4 sh_wp[128];   // Wp[0:512] as float4
    const int tid = threadIdx.x;
    if (tid < 128) sh_wp[tid] = ((const float4*)Wp)[tid];
    __syncthreads();

    const int w    = blockIdx.x * 8 + (tid >> 5);   // global warp id
    const int m    = w >> 10;
    const int p    = w & (NPOS - 1);
    const int lane = tid & 31;

    const float4* row = (const float4*)(emb + ((size_t)(m * NPOS + p)) * E_);

    float a0 = 0.f, a1 = 0.f;
    // 64 float4 chunks per row; lane handles chunks {lane, lane+32}
    {
        float4 v = row[lane];
        float4 wa = sh_wp[lane];        // Wp[0:256]
        float4 wb = sh_wp[64 + lane];   // Wp[256:512]
        a0 += v.x*wa.x + v.y*wa.y + v.z*wa.z + v.w*wa.w;
        a1 += v.x*wb.x + v.y*wb.y + v.z*wb.z + v.w*wb.w;
        v  = row[lane + 32];
        wa = sh_wp[lane + 32];
        wb = sh_wp[96 + lane];
        a0 += v.x*wa.x + v.y*wa.y + v.z*wa.z + v.w*wa.w;
        a1 += v.x*wb.x + v.y*wb.y + v.z*wb.z + v.w*wb.w;
    }
    #pragma unroll
    for (int o = 16; o; o >>= 1) {
        a0 += __shfl_xor_sync(0xffffffffu, a0, o);
        a1 += __shfl_xor_sync(0xffffffffu, a1, o);
    }
    if (lane == 0) {
        ((float2*)g_tab)[m * NPOS + p] = make_float2(a0, a1);
    }
}

// ---------------------------------------------------------------------------
// Kernel C: policy fill.  <<<512, 256>>>; each block serves one m (64 blocks/m)
//   and stages that m's 8 KB table slice in shared.
// ---------------------------------------------------------------------------
__global__ void policy_kernel(const int* __restrict__ sel,
                              float* __restrict__ out)
{
    __shared__ float sh_tab[NPOS * 2];
    const int m     = blockIdx.x >> 6;
    const int lbase = (blockIdx.x & 63) * 256;

    const float* tabm = g_tab + m * NPOS * 2;
    for (int i = threadIdx.x; i < NPOS * 2; i += 256) sh_tab[i] = tabm[i];
    __syncthreads();

    const int l = lbase + threadIdx.x;
    // selection_moves[l] = {r0, c0, r1, c1}
    const int4 mv = ((const int4*)sel)[l];
    const int p0 = (mv.x << 5) | mv.y;
    const int p1 = (mv.z << 5) | mv.w;
    out[m * POL_STRIDE + l] = sh_tab[p0 * 2] + sh_tab[p1 * 2 + 1] + g_clsdot[m];
}

// ---------------------------------------------------------------------------
extern "C" void kernel_launch(void* const* d_in, const int* in_sizes, int n_in,
                              void* d_out, int out_size)
{
    const float* emb  = (const float*)d_in[0];   // (8,32,32,256)
    const float* cls  = (const float*)d_in[1];   // (8,256)
    const int*   sel  = (const int*)  d_in[2];   // (16384,2,2)
    const int*   sidx = (const int*)  d_in[3];   // (8,)
    const float* Wp   = (const float*)d_in[4];   // (768,1)
    const float* bp   = (const float*)d_in[5];
    const float* Wv1  = (const float*)d_in[6];
    const float* bv1  = (const float*)d_in[7];
    const float* Wv2  = (const float*)d_in[8];
    const float* bv2  = (const float*)d_in[9];
    const float* Ws1  = (const float*)d_in[10];
    const float* bs1  = (const float*)d_in[11];
    const float* Ws2  = (const float*)d_in[12];
    const float* bs2  = (const float*)d_in[13];
    float* out = (float*)d_out;

    mlp_kernel<<<2, 256>>>(cls, sidx, Wp, bp, Wv1, bv1, Wv2, bv2,
                           Ws1, bs1, Ws2, bs2, out);
    table_kernel<<<1024, 256>>>(emb, Wp);
    policy_kernel<<<512, 256>>>(sel, out);
}

// round 5
// speedup vs baseline: 1.8555x; 1.8555x over previous
#include <cuda_runtime.h>

#define M_        8
#define E_        256
#define H_        256
#define L_        16384
#define NPOS      1024          // 32*32
#define NSPECIAL_ 32
#define SIDX_     8
#define NPLAYERS_ 4
#define POL_STRIDE (L_ + SIDX_) // 16392
#define NCHUNK    8             // e-chunks per head in stage 1
#define ECHUNK    (E_ / NCHUNK) // 32

// device scratch (no cudaMalloc allowed)
__device__ float g_tab[M_ * NPOS * 2];               // [m][p][k]       64 KB
__device__ float g_clsdot[M_];                       // cls part of policy dot (+bp)
__device__ float g_part[2 * NCHUNK * M_ * H_];       // [head][chunk][m][j]  128 KB

// ---------------------------------------------------------------------------
// Launch 1: grid = 1024 (table) + 16 (mlp stage1 partials) + 1 (cls_dot)
// ---------------------------------------------------------------------------
__global__ void __launch_bounds__(256)
fused_kernel(const float* __restrict__ emb,
             const float* __restrict__ cls,
             const float* __restrict__ Wp,
             const float* __restrict__ bp,
             const float* __restrict__ Ws1,
             const float* __restrict__ Wv1)
{
    __shared__ float sh[M_ * E_];       // 8 KB, reused per role
    const int tid = threadIdx.x;
    const int bx  = blockIdx.x;

    if (bx < 1024) {
        // ---- per-position dot table: warp per (m,p), reads embedding once ----
        float4* sh_wp = (float4*)sh;    // Wp[0:512] as 128 float4
        if (tid < 128) sh_wp[tid] = ((const float4*)Wp)[tid];
        __syncthreads();

        const int w    = bx * 8 + (tid >> 5);
        const int m    = w >> 10;
        const int p    = w & (NPOS - 1);
        const int lane = tid & 31;

        const float4* row = (const float4*)(emb + ((size_t)(m * NPOS + p)) * E_);

        float a0 = 0.f, a1 = 0.f;
        float4 v  = row[lane];
        float4 wa = sh_wp[lane];
        float4 wb = sh_wp[64 + lane];
        a0 += v.x*wa.x + v.y*wa.y + v.z*wa.z + v.w*wa.w;
        a1 += v.x*wb.x + v.y*wb.y + v.z*wb.z + v.w*wb.w;
        v  = row[lane + 32];
        wa = sh_wp[lane + 32];
        wb = sh_wp[96 + lane];
        a0 += v.x*wa.x + v.y*wa.y + v.z*wa.z + v.w*wa.w;
        a1 += v.x*wb.x + v.y*wb.y + v.z*wb.z + v.w*wb.w;

        #pragma unroll
        for (int o = 16; o; o >>= 1) {
            a0 += __shfl_xor_sync(0xffffffffu, a0, o);
            a1 += __shfl_xor_sync(0xffffffffu, a1, o);
        }
        if (lane == 0)
            ((float2*)g_tab)[m * NPOS + p] = make_float2(a0, a1);
    }
    else if (bx < 1024 + 16) {
        // ---- MLP stage 1: partial h over one e-chunk of one head ----
        const int idx   = bx - 1024;
        const int head  = idx >> 3;          // 0=special(Ws1), 1=value(Wv1)
        const int chunk = idx & 7;
        const float* __restrict__ W1 = head ? Wv1 : Ws1;

        for (int i = tid; i < M_ * E_; i += 256) sh[i] = cls[i];
        __syncthreads();

        const int e0 = chunk * ECHUNK;
        float acc[M_];
        #pragma unroll
        for (int m = 0; m < M_; m++) acc[m] = 0.f;

        #pragma unroll 8
        for (int ee = 0; ee < ECHUNK; ee++) {
            const float wv = __ldg(&W1[(e0 + ee) * H_ + tid]);
            #pragma unroll
            for (int m = 0; m < M_; m++) acc[m] += sh[m * E_ + e0 + ee] * wv;
        }

        float* dst = g_part + ((head * NCHUNK + chunk) * M_) * H_;
        #pragma unroll
        for (int m = 0; m < M_; m++) dst[m * H_ + tid] = acc[m];
    }
    else {
        // ---- cls_dot: warp per m ----
        for (int i = tid; i < M_ * E_; i += 256) sh[i] = cls[i];
        __syncthreads();
        const int w = tid >> 5, lane = tid & 31;
        float a = 0.f;
        for (int e = lane; e < E_; e += 32)
            a += sh[w * E_ + e] * __ldg(&Wp[2 * E_ + e]);
        #pragma unroll
        for (int o = 16; o; o >>= 1) a += __shfl_xor_sync(0xffffffffu, a, o);
        if (lane == 0) g_clsdot[w] = a + __ldg(bp);
    }
}

// ---------------------------------------------------------------------------
// Launch 2: grid = 512 (policy fill) + 2 (head finish).
//   Policy blocks: one m per 64-block group, table staged in smem.
//   Head blocks: reduce g_part partials, relu, second layer, write outputs.
// ---------------------------------------------------------------------------
__global__ void __launch_bounds__(256)
finish_kernel(const int*   __restrict__ sel,
              const int*   __restrict__ sidx,
              const float* __restrict__ bv1,
              const float* __restrict__ Wv2, const float* __restrict__ bv2,
              const float* __restrict__ bs1,
              const float* __restrict__ Ws2, const float* __restrict__ bs2,
              float* __restrict__ out)
{
    const int tid = threadIdx.x;
    const int bx  = blockIdx.x;

    if (bx < 512) {
        // ---- policy fill ----
        __shared__ float sh_tab[NPOS * 2];
        __shared__ float sh_cd;
        const int m     = bx >> 6;
        const int lbase = (bx & 63) * 256;

        const float* tabm = g_tab + m * NPOS * 2;
        for (int i = tid; i < NPOS * 2; i += 256) sh_tab[i] = tabm[i];
        if (tid == 0) sh_cd = g_clsdot[m];
        __syncthreads();

        const int l = lbase + tid;
        const int4 mv = ((const int4*)sel)[l];     // {r0,c0,r1,c1}
        const int p0 = (mv.x << 5) | mv.y;
        const int p1 = (mv.z << 5) | mv.w;
        out[m * POL_STRIDE + l] = sh_tab[p0 * 2] + sh_tab[p1 * 2 + 1] + sh_cd;
    } else {
        // ---- head finish ----
        __shared__ float sh_h[M_][H_];              //  8 KB
        __shared__ float sh_w[H_ * NSPECIAL_];      // 32 KB (max of both heads)
        __shared__ float sh_spec[M_][NSPECIAL_];
        const int head = bx - 512;                  // 0=special, 1=value

        if (head == 0) {
            for (int i = tid; i < H_ * NSPECIAL_; i += 256) sh_w[i] = Ws2[i];
        } else {
            for (int i = tid; i < H_ * NPLAYERS_; i += 256) sh_w[i] = Wv2[i];
        }

        // hidden = relu(bias + sum of partials); thread owns column j = tid
        const float b = head ? __ldg(&bv1[tid]) : __ldg(&bs1[tid]);
        const float* part = g_part + (head * NCHUNK * M_) * H_;
        #pragma unroll
        for (int m = 0; m < M_; m++) {
            float a = b;
            #pragma unroll
            for (int c = 0; c < NCHUNK; c++)
                a += part[(c * M_ + m) * H_ + tid];
            sh_h[m][tid] = fmaxf(a, 0.f);
        }
        __syncthreads();

        if (head == 0) {
            // special_all = h @ Ws2 + bs2 : 8m x 32s = 256 threads
            const int m = tid >> 5, s = tid & 31;
            float a = __ldg(&bs2[s]);
            #pragma unroll 8
            for (int j = 0; j < H_; j++)
                a += sh_h[m][j] * sh_w[j * NSPECIAL_ + s];
            sh_spec[m][s] = a;
            __syncthreads();
            if (tid < M_ * SIDX_) {
                const int mm = tid / SIDX_, i = tid % SIDX_;
                out[mm * POL_STRIDE + L_ + i] = sh_spec[mm][__ldg(&sidx[i])];
            }
        } else {
            if (tid < M_ * NPLAYERS_) {
                const int m = tid / NPLAYERS_, n = tid % NPLAYERS_;
                float a = __ldg(&bv2[n]);
                #pragma unroll 8
                for (int j = 0; j < H_; j++)
                    a += sh_h[m][j] * sh_w[j * NPLAYERS_ + n];
                out[M_ * POL_STRIDE + m * NPLAYERS_ + n] = a;
            }
        }
    }
}

// ---------------------------------------------------------------------------
extern "C" void kernel_launch(void* const* d_in, const int* in_sizes, int n_in,
                              void* d_out, int out_size)
{
    const float* emb  = (const float*)d_in[0];
    const float* cls  = (const float*)d_in[1];
    const int*   sel  = (const int*)  d_in[2];
    const int*   sidx = (const int*)  d_in[3];
    const float* Wp   = (const float*)d_in[4];
    const float* bp   = (const float*)d_in[5];
    const float* Wv1  = (const float*)d_in[6];
    const float* bv1  = (const float*)d_in[7];
    const float* Wv2  = (const float*)d_in[8];
    const float* bv2  = (const float*)d_in[9];
    const float* Ws1  = (const float*)d_in[10];
    const float* bs1  = (const float*)d_in[11];
    const float* Ws2  = (const float*)d_in[12];
    const float* bs2  = (const float*)d_in[13];
    float* out = (float*)d_out;

    fused_kernel<<<1024 + 16 + 1, 256>>>(emb, cls, Wp, bp, Ws1, Wv1);
    finish_kernel<<<512 + 2, 256>>>(sel, sidx, bv1, Wv2, bv2, bs1, Ws2, bs2, out);
}